// round 15
// baseline (speedup 1.0000x reference)
#include <cuda_runtime.h>
#include <cuda_fp16.h>
#include <cstdint>

// ===================== problem sizes =====================
#define SEQ   2048
#define HID   8192
#define NTOT  10240          // 8192 q + 1024 k + 1024 v
#define Q_ELEMS   ((size_t)64 * SEQ * 128)
#define KV_ELEMS  ((size_t)8  * SEQ * 128)

// ===================== scratch (fp16) =====================
__device__ unsigned short g_A[(size_t)SEQ * HID];     // [SEQ][HID]  (M-major)
__device__ unsigned short g_B[(size_t)HID * NTOT];    // [HID][NTOT] (K-major)

// ===================== conversion kernels (R11-proven) =====================
__global__ void convert_x_kernel(const float* __restrict__ x) {
    size_t n4 = (size_t)SEQ * HID / 4;
    for (size_t i = (size_t)blockIdx.x * blockDim.x + threadIdx.x;
         i < n4; i += (size_t)gridDim.x * blockDim.x) {
        float4 v = reinterpret_cast<const float4*>(x)[i];
        ushort4 h;
        h.x = __half_as_ushort(__float2half_rn(v.x));
        h.y = __half_as_ushort(__float2half_rn(v.y));
        h.z = __half_as_ushort(__float2half_rn(v.z));
        h.w = __half_as_ushort(__float2half_rn(v.w));
        reinterpret_cast<ushort4*>(g_A)[i] = h;
    }
}

__device__ __forceinline__ uint32_t pack2h(float a, float b) {
    uint32_t lo = __half_as_ushort(__float2half_rn(a));
    uint32_t hi = __half_as_ushort(__float2half_rn(b));
    return lo | (hi << 16);
}

// All three weights in ONE launch. blockIdx.y = k row; 10 blocks of 128 thr
// cover 1280 8-float chunks = 10240 columns. Region select by column.
__global__ void convert_w_all_kernel(const float* __restrict__ wq,
                                     const float* __restrict__ wk,
                                     const float* __restrict__ wv) {
    int k = blockIdx.y;
    int t = blockIdx.x * blockDim.x + threadIdx.x;    // 8-float chunk, 0..1279
    int n = t * 8;
    const float* src;
    if (n < 8192)       src = wq + (size_t)k * 8192 + n;
    else if (n < 9216)  src = wk + (size_t)k * 1024 + (n - 8192);
    else                src = wv + (size_t)k * 1024 + (n - 9216);
    float4 v0 = reinterpret_cast<const float4*>(src)[0];
    float4 v1 = reinterpret_cast<const float4*>(src)[1];
    uint4 h;
    h.x = pack2h(v0.x, v0.y);
    h.y = pack2h(v0.z, v0.w);
    h.z = pack2h(v1.x, v1.y);
    h.w = pack2h(v1.z, v1.w);
    *reinterpret_cast<uint4*>(&g_B[(size_t)k * NTOT + n]) = h;
}

// ===================== GEMM kernel =====================
// CTA tile: 128M x 128N, BK=64. 128 threads, warp grid 2x2, warp tile 64x64.
// A stage: 128 rows(m) x 128B(k). B stage: 64 rows(k) x 256B(n).
// 3 stages x 32KB = 96KB smem -> 2 CTAs/SM (255-reg budget per thread).
// Register-fragment double buffering across ks-steps (R14-proven).
#define GEMM_THREADS 128
#define STAGES       3
#define A_BYTES      16384
#define B_BYTES      16384
#define STAGE_BYTES  (A_BYTES + B_BYTES)     // 32KB
#define GEMM_SMEM    (STAGES * STAGE_BYTES + 1024)

#define LDSM4(r0, r1, r2, r3, addr) \
    asm volatile("ldmatrix.sync.aligned.m8n8.x4.shared.b16 {%0,%1,%2,%3}, [%4];" \
        : "=r"(r0), "=r"(r1), "=r"(r2), "=r"(r3) : "r"(addr))

#define LDSM4T(r0, r1, r2, r3, addr) \
    asm volatile("ldmatrix.sync.aligned.m8n8.x4.trans.shared.b16 {%0,%1,%2,%3}, [%4];" \
        : "=r"(r0), "=r"(r1), "=r"(r2), "=r"(r3) : "r"(addr))

#define MMA_F16(d, a, b0, b1) \
    asm volatile("mma.sync.aligned.m16n8k16.row.col.f32.f16.f16.f32 " \
        "{%0,%1,%2,%3},{%4,%5,%6,%7},{%8,%9},{%0,%1,%2,%3};" \
        : "+f"((d)[0]), "+f"((d)[1]), "+f"((d)[2]), "+f"((d)[3]) \
        : "r"((a)[0]), "r"((a)[1]), "r"((a)[2]), "r"((a)[3]), "r"(b0), "r"(b1))

__device__ __forceinline__ uint32_t smem_to_u32(const void* p) {
    uint32_t addr;
    asm("{ .reg .u64 t; cvta.to.shared.u64 t, %1; cvt.u32.u64 %0, t; }"
        : "=r"(addr) : "l"(p));
    return addr;
}

// A tile: 128 rows x 128B, SW128-swizzled (8 chunks of 16B per row).
__device__ __forceinline__ void cp_tile_a(uint32_t sdst, int m0, int k0, int tid) {
    const char* g = (const char*)(g_A + (size_t)m0 * HID + k0);
    #pragma unroll
    for (int i = 0; i < 8; ++i) {
        int idx = i * GEMM_THREADS + tid;   // 0..1023
        int r = idx >> 3;
        int c = idx & 7;
        uint32_t off = (uint32_t)(r * 128 + ((c ^ (r & 7)) * 16));
        const char* src = g + (size_t)r * (HID * 2) + c * 16;
        asm volatile("cp.async.cg.shared.global [%0], [%1], 16;"
                     :: "r"(sdst + off), "l"(src) : "memory");
    }
}

// B tile: 64 rows(k) x 256B(n), per-128B-half XOR swizzle keyed on k-row.
__device__ __forceinline__ void cp_tile_b(uint32_t sdst, int n0, int k0, int tid) {
    const char* g = (const char*)(g_B + (size_t)k0 * NTOT + n0);
    #pragma unroll
    for (int i = 0; i < 8; ++i) {
        int idx = i * GEMM_THREADS + tid;   // 0..1023
        int r = idx >> 4;                   // k row 0..63
        int c = idx & 15;                   // 16B chunk 0..15
        uint32_t off = (uint32_t)(r * 256 + (c & 8) * 16
                                  + (((c & 7) ^ (r & 7)) * 16));
        const char* src = g + (size_t)r * (NTOT * 2) + c * 16;
        asm volatile("cp.async.cg.shared.global [%0], [%1], 16;"
                     :: "r"(sdst + off), "l"(src) : "memory");
    }
}

__device__ __forceinline__ void load_stage(uint32_t sstage, int m0, int n0,
                                           int k0, int tid) {
    cp_tile_a(sstage,           m0, k0, tid);
    cp_tile_b(sstage + A_BYTES, n0, k0, tid);
    asm volatile("cp.async.commit_group;" ::: "memory");
}

__global__ __launch_bounds__(GEMM_THREADS, 2)
void qkv_gemm_kernel(float* __restrict__ out) {
    extern __shared__ char smem_raw[];
    char* sm = (char*)(((uintptr_t)smem_raw + 1023) & ~(uintptr_t)1023);
    uint32_t sbase = smem_to_u32(sm);

    const int tid  = threadIdx.x;
    const int lane = tid & 31;
    const int wid  = tid >> 5;
    const int warp_m = wid & 1;    // 2 warps along M (64 rows each)
    const int warp_n = wid >> 1;   // 2 warps along N (64 cols each)

    const int m0 = (blockIdx.x & 15) << 7;        // 16 M-tiles (M-fastest)
    const int n0 = (int)(blockIdx.x >> 4) << 7;   // 80 N-tiles

    float acc[4][8][4];
    #pragma unroll
    for (int i = 0; i < 4; ++i)
        #pragma unroll
        for (int j = 0; j < 8; ++j)
            #pragma unroll
            for (int r = 0; r < 4; ++r) acc[i][j][r] = 0.f;

    // A ldmatrix lane roles (non-trans, [M][K] tile, 128B rows)
    const int a_row_l = lane & 15;
    const int a_chi   = lane >> 4;
    // B ldmatrix.trans lane roles ([K][N] tile, 256B rows)
    const int b_krow  = (lane & 7) + ((lane >> 3) & 1) * 8;
    const int b_nchi  = lane >> 4;               // 0/1 -> n8 group within n16

    // Double-buffered register fragments
    uint32_t af[2][4][4];
    uint32_t bf[2][8][2];

    // prologue: prefetch STAGES-1 stages
    load_stage(sbase + 0 * STAGE_BYTES, m0, n0, 0,  tid);
    load_stage(sbase + 1 * STAGE_BYTES, m0, n0, 64, tid);

    const int NKT = HID / 64;   // 128
    for (int kt = 0; kt < NKT; ++kt) {
        if (kt + 2 < NKT)
            asm volatile("cp.async.wait_group 1;" ::: "memory");
        else
            asm volatile("cp.async.wait_group 0;" ::: "memory");
        __syncthreads();

        if (kt + 2 < NKT)
            load_stage(sbase + ((kt + 2) % STAGES) * STAGE_BYTES,
                       m0, n0, (kt + 2) * 64, tid);

        const uint32_t st = sbase + (kt % STAGES) * STAGE_BYTES;
        const uint32_t sa = st;
        const uint32_t sb = st + A_BYTES;

        // frag loader for one ks step into parity buffer p
        auto load_frags = [&](int ks, int p) {
            #pragma unroll
            for (int mf = 0; mf < 4; ++mf) {
                int row = warp_m * 64 + mf * 16 + a_row_l;
                int c   = 2 * ks + a_chi;
                uint32_t off = (uint32_t)(row * 128 + ((c ^ (row & 7)) * 16));
                LDSM4(af[p][mf][0], af[p][mf][1], af[p][mf][2], af[p][mf][3],
                      sa + off);
            }
            #pragma unroll
            for (int jp = 0; jp < 4; ++jp) {
                int krow = ks * 16 + b_krow;
                int nb   = warp_n * 128 + jp * 32 + b_nchi * 16;
                uint32_t off = (uint32_t)(krow * 256 + (nb & 128)
                               + ((((nb >> 4) & 7) ^ (krow & 7)) * 16));
                LDSM4T(bf[p][2*jp][0], bf[p][2*jp][1],
                       bf[p][2*jp+1][0], bf[p][2*jp+1][1], sb + off);
            }
        };

        load_frags(0, 0);
        #pragma unroll
        for (int ks = 0; ks < 4; ++ks) {
            const int cur = ks & 1;
            if (ks < 3) load_frags(ks + 1, cur ^ 1);
            #pragma unroll
            for (int mf = 0; mf < 4; ++mf)
                #pragma unroll
                for (int j = 0; j < 8; ++j)
                    MMA_F16(acc[mf][j], af[cur][mf], bf[cur][j][0], bf[cur][j][1]);
        }
    }

    // ---- epilogue: scatter accumulators to q/k/v head layout ----
    size_t obase;
    if (n0 < 8192)
        obase = (size_t)(n0 >> 7) * ((size_t)SEQ * 128);
    else if (n0 < 9216)
        obase = Q_ELEMS + (size_t)((n0 - 8192) >> 7) * ((size_t)SEQ * 128);
    else
        obase = Q_ELEMS + KV_ELEMS + (size_t)((n0 - 9216) >> 7) * ((size_t)SEQ * 128);

    const int rbase = m0 + warp_m * 64 + (lane >> 2);
    const int cbase = warp_n * 64 + (lane & 3) * 2;
    #pragma unroll
    for (int mf = 0; mf < 4; ++mf) {
        #pragma unroll
        for (int j = 0; j < 8; ++j) {
            int m = rbase + mf * 16;
            int c = cbase + j * 8;
            float* p0 = out + obase + (size_t)m * 128 + c;
            p0[0] = acc[mf][j][0];
            p0[1] = acc[mf][j][1];
            float* p1 = p0 + 8 * 128;
            p1[0] = acc[mf][j][2];
            p1[1] = acc[mf][j][3];
        }
    }
}

// ===================== host launcher =====================
extern "C" void kernel_launch(void* const* d_in, const int* in_sizes, int n_in,
                              void* d_out, int out_size) {
    const float* x = nullptr; const float* wq = nullptr;
    const float* wk = nullptr; const float* wv = nullptr;
    for (int i = 0; i < n_in; ++i) {
        long long sz = in_sizes[i];
        const float* p = (const float*)d_in[i];
        if (sz == (long long)SEQ * HID)       { if (!x) x = p; }
        else if (sz == (long long)HID * 8192) { if (!wq) wq = p; }
        else if (sz == (long long)HID * 1024) { if (!wk) wk = p; else if (!wv) wv = p; }
    }
    float* out = (float*)d_out;

    cudaFuncSetAttribute(qkv_gemm_kernel,
                         cudaFuncAttributeMaxDynamicSharedMemorySize, GEMM_SMEM);

    // 1) convert activations to fp16 (streaming)
    convert_x_kernel<<<2048, 256>>>(x);

    // 2) all weights -> K-major fp16 g_B in one launch
    convert_w_all_kernel<<<dim3(10, HID), 128>>>(wq, wk, wv);

    // 3) fp16 HMMA GEMM (128x128 tile, 2 CTAs/SM, frag-DB) + q/k/v scatter
    qkv_gemm_kernel<<<16 * 80, GEMM_THREADS, GEMM_SMEM>>>(out);
}

// round 16
// speedup vs baseline: 1.0760x; 1.0760x over previous
#include <cuda_runtime.h>
#include <cuda_fp16.h>
#include <cstdint>

// ===================== problem sizes =====================
#define SEQ   2048
#define HID   8192
#define NTOT  10240          // 8192 q + 1024 k + 1024 v
#define Q_ELEMS   ((size_t)64 * SEQ * 128)
#define KV_ELEMS  ((size_t)8  * SEQ * 128)

// ===================== scratch (fp16) =====================
__device__ unsigned short g_A[(size_t)SEQ * HID];     // [SEQ][HID]  (M-major)
__device__ unsigned short g_B[(size_t)HID * NTOT];    // [HID][NTOT] (K-major)

// ===================== conversion kernels (R11-proven) =====================
__global__ void convert_x_kernel(const float* __restrict__ x) {
    size_t n4 = (size_t)SEQ * HID / 4;
    for (size_t i = (size_t)blockIdx.x * blockDim.x + threadIdx.x;
         i < n4; i += (size_t)gridDim.x * blockDim.x) {
        float4 v = reinterpret_cast<const float4*>(x)[i];
        ushort4 h;
        h.x = __half_as_ushort(__float2half_rn(v.x));
        h.y = __half_as_ushort(__float2half_rn(v.y));
        h.z = __half_as_ushort(__float2half_rn(v.z));
        h.w = __half_as_ushort(__float2half_rn(v.w));
        reinterpret_cast<ushort4*>(g_A)[i] = h;
    }
}

__device__ __forceinline__ uint32_t pack2h(float a, float b) {
    uint32_t lo = __half_as_ushort(__float2half_rn(a));
    uint32_t hi = __half_as_ushort(__float2half_rn(b));
    return lo | (hi << 16);
}

// All three weights in ONE launch. blockIdx.y = k row; 10 blocks of 128 thr
// cover 1280 8-float chunks = 10240 columns. Region select by column.
__global__ void convert_w_all_kernel(const float* __restrict__ wq,
                                     const float* __restrict__ wk,
                                     const float* __restrict__ wv) {
    int k = blockIdx.y;
    int t = blockIdx.x * blockDim.x + threadIdx.x;    // 8-float chunk, 0..1279
    int n = t * 8;
    const float* src;
    if (n < 8192)       src = wq + (size_t)k * 8192 + n;
    else if (n < 9216)  src = wk + (size_t)k * 1024 + (n - 8192);
    else                src = wv + (size_t)k * 1024 + (n - 9216);
    float4 v0 = reinterpret_cast<const float4*>(src)[0];
    float4 v1 = reinterpret_cast<const float4*>(src)[1];
    uint4 h;
    h.x = pack2h(v0.x, v0.y);
    h.y = pack2h(v0.z, v0.w);
    h.z = pack2h(v1.x, v1.y);
    h.w = pack2h(v1.z, v1.w);
    *reinterpret_cast<uint4*>(&g_B[(size_t)k * NTOT + n]) = h;
}

// ===================== GEMM kernel =====================
// R11 config (128M x 64N, BK=64, 3 stages, 3 CTAs/SM, 12 warps/SM)
// + register-fragment double buffering across the 4 ks-steps (R14 winner).
#define GEMM_THREADS 128
#define STAGES       3
#define A_BYTES      16384
#define B_BYTES      8192
#define STAGE_BYTES  (A_BYTES + B_BYTES)     // 24KB
#define GEMM_SMEM    (STAGES * STAGE_BYTES + 1024)

#define LDSM4(r0, r1, r2, r3, addr) \
    asm volatile("ldmatrix.sync.aligned.m8n8.x4.shared.b16 {%0,%1,%2,%3}, [%4];" \
        : "=r"(r0), "=r"(r1), "=r"(r2), "=r"(r3) : "r"(addr))

#define LDSM4T(r0, r1, r2, r3, addr) \
    asm volatile("ldmatrix.sync.aligned.m8n8.x4.trans.shared.b16 {%0,%1,%2,%3}, [%4];" \
        : "=r"(r0), "=r"(r1), "=r"(r2), "=r"(r3) : "r"(addr))

#define MMA_F16(d, a, b0, b1) \
    asm volatile("mma.sync.aligned.m16n8k16.row.col.f32.f16.f16.f32 " \
        "{%0,%1,%2,%3},{%4,%5,%6,%7},{%8,%9},{%0,%1,%2,%3};" \
        : "+f"((d)[0]), "+f"((d)[1]), "+f"((d)[2]), "+f"((d)[3]) \
        : "r"((a)[0]), "r"((a)[1]), "r"((a)[2]), "r"((a)[3]), "r"(b0), "r"(b1))

__device__ __forceinline__ uint32_t smem_to_u32(const void* p) {
    uint32_t addr;
    asm("{ .reg .u64 t; cvta.to.shared.u64 t, %1; cvt.u32.u64 %0, t; }"
        : "=r"(addr) : "l"(p));
    return addr;
}

// A tile: 128 rows x 128B, SW128-swizzled (8 chunks of 16B per row).
__device__ __forceinline__ void cp_tile_a(uint32_t sdst, int m0, int k0, int tid) {
    const char* g = (const char*)(g_A + (size_t)m0 * HID + k0);
    #pragma unroll
    for (int i = 0; i < 8; ++i) {
        int idx = i * GEMM_THREADS + tid;   // 0..1023
        int r = idx >> 3;
        int c = idx & 7;
        uint32_t off = (uint32_t)(r * 128 + ((c ^ (r & 7)) * 16));
        const char* src = g + (size_t)r * (HID * 2) + c * 16;
        asm volatile("cp.async.cg.shared.global [%0], [%1], 16;"
                     :: "r"(sdst + off), "l"(src) : "memory");
    }
}

// B tile: 64 rows(k) x 128B(n=64 fp16), SW128 swizzle keyed on k-row.
__device__ __forceinline__ void cp_tile_b(uint32_t sdst, int n0, int k0, int tid) {
    const char* g = (const char*)(g_B + (size_t)k0 * NTOT + n0);
    #pragma unroll
    for (int i = 0; i < 4; ++i) {
        int idx = i * GEMM_THREADS + tid;   // 0..511
        int r = idx >> 3;                   // k row 0..63
        int c = idx & 7;                    // 16B chunk 0..7
        uint32_t off = (uint32_t)(r * 128 + ((c ^ (r & 7)) * 16));
        const char* src = g + (size_t)r * (NTOT * 2) + c * 16;
        asm volatile("cp.async.cg.shared.global [%0], [%1], 16;"
                     :: "r"(sdst + off), "l"(src) : "memory");
    }
}

__device__ __forceinline__ void load_stage(uint32_t sstage, int m0, int n0,
                                           int k0, int tid) {
    cp_tile_a(sstage,           m0, k0, tid);
    cp_tile_b(sstage + A_BYTES, n0, k0, tid);
    asm volatile("cp.async.commit_group;" ::: "memory");
}

__global__ __launch_bounds__(GEMM_THREADS, 3)
void qkv_gemm_kernel(float* __restrict__ out) {
    extern __shared__ char smem_raw[];
    char* sm = (char*)(((uintptr_t)smem_raw + 1023) & ~(uintptr_t)1023);
    uint32_t sbase = smem_to_u32(sm);

    const int tid  = threadIdx.x;
    const int lane = tid & 31;
    const int wid  = tid >> 5;
    const int warp_m = wid & 1;    // 2 warps along M (64 rows each)
    const int warp_n = wid >> 1;   // 2 warps along N (32 cols each)

    const int m0 = (blockIdx.x & 15) << 7;        // 16 M-tiles (M-fastest)
    const int n0 = (int)(blockIdx.x >> 4) << 6;   // 160 N-tiles of 64

    float acc[4][4][4];
    #pragma unroll
    for (int i = 0; i < 4; ++i)
        #pragma unroll
        for (int j = 0; j < 4; ++j)
            #pragma unroll
            for (int r = 0; r < 4; ++r) acc[i][j][r] = 0.f;

    // A ldmatrix lane roles (non-trans, [M][K] tile, 128B rows)
    const int a_row_l = lane & 15;
    const int a_chi   = lane >> 4;
    // B ldmatrix.trans lane roles ([K][N] tile, 128B rows)
    const int b_krow  = (lane & 7) + ((lane >> 3) & 1) * 8;
    const int b_nchi  = lane >> 4;               // 0/1 -> n8 group within n16

    // Double-buffered register fragments
    uint32_t af[2][4][4];
    uint32_t bf[2][4][2];

    // prologue: prefetch STAGES-1 stages
    load_stage(sbase + 0 * STAGE_BYTES, m0, n0, 0,  tid);
    load_stage(sbase + 1 * STAGE_BYTES, m0, n0, 64, tid);

    const int NKT = HID / 64;   // 128
    for (int kt = 0; kt < NKT; ++kt) {
        if (kt + 2 < NKT)
            asm volatile("cp.async.wait_group 1;" ::: "memory");
        else
            asm volatile("cp.async.wait_group 0;" ::: "memory");
        __syncthreads();

        if (kt + 2 < NKT)
            load_stage(sbase + ((kt + 2) % STAGES) * STAGE_BYTES,
                       m0, n0, (kt + 2) * 64, tid);

        const uint32_t st = sbase + (kt % STAGES) * STAGE_BYTES;
        const uint32_t sa = st;
        const uint32_t sb = st + A_BYTES;

        // frag loader for one ks step into parity buffer p
        auto load_frags = [&](int ks, int p) {
            #pragma unroll
            for (int mf = 0; mf < 4; ++mf) {
                int row = warp_m * 64 + mf * 16 + a_row_l;
                int c   = 2 * ks + a_chi;
                uint32_t off = (uint32_t)(row * 128 + ((c ^ (row & 7)) * 16));
                LDSM4(af[p][mf][0], af[p][mf][1], af[p][mf][2], af[p][mf][3],
                      sa + off);
            }
            #pragma unroll
            for (int jp = 0; jp < 2; ++jp) {
                int krow = ks * 16 + b_krow;
                int nb   = warp_n * 64 + jp * 32 + b_nchi * 16;
                uint32_t off = (uint32_t)(krow * 128
                               + ((((nb >> 4) & 7) ^ (krow & 7)) * 16));
                LDSM4T(bf[p][2*jp][0], bf[p][2*jp][1],
                       bf[p][2*jp+1][0], bf[p][2*jp+1][1], sb + off);
            }
        };

        load_frags(0, 0);
        #pragma unroll
        for (int ks = 0; ks < 4; ++ks) {
            const int cur = ks & 1;
            if (ks < 3) load_frags(ks + 1, cur ^ 1);
            #pragma unroll
            for (int mf = 0; mf < 4; ++mf)
                #pragma unroll
                for (int j = 0; j < 4; ++j)
                    MMA_F16(acc[mf][j], af[cur][mf], bf[cur][j][0], bf[cur][j][1]);
        }
    }

    // ---- epilogue: scatter accumulators to q/k/v head layout ----
    // N-tile (64 cols) = half of one 128-wide head; head index = n0>>7.
    size_t obase;
    if (n0 < 8192)
        obase = (size_t)(n0 >> 7) * ((size_t)SEQ * 128);
    else if (n0 < 9216)
        obase = Q_ELEMS + (size_t)((n0 - 8192) >> 7) * ((size_t)SEQ * 128);
    else
        obase = Q_ELEMS + KV_ELEMS + (size_t)((n0 - 9216) >> 7) * ((size_t)SEQ * 128);
    const int chalf = n0 & 64;   // which half of the head

    const int rbase = m0 + warp_m * 64 + (lane >> 2);
    const int cbase = chalf + warp_n * 32 + (lane & 3) * 2;
    #pragma unroll
    for (int mf = 0; mf < 4; ++mf) {
        #pragma unroll
        for (int j = 0; j < 4; ++j) {
            int m = rbase + mf * 16;
            int c = cbase + j * 8;
            float* p0 = out + obase + (size_t)m * 128 + c;
            p0[0] = acc[mf][j][0];
            p0[1] = acc[mf][j][1];
            float* p1 = p0 + 8 * 128;
            p1[0] = acc[mf][j][2];
            p1[1] = acc[mf][j][3];
        }
    }
}

// ===================== host launcher =====================
extern "C" void kernel_launch(void* const* d_in, const int* in_sizes, int n_in,
                              void* d_out, int out_size) {
    const float* x = nullptr; const float* wq = nullptr;
    const float* wk = nullptr; const float* wv = nullptr;
    for (int i = 0; i < n_in; ++i) {
        long long sz = in_sizes[i];
        const float* p = (const float*)d_in[i];
        if (sz == (long long)SEQ * HID)       { if (!x) x = p; }
        else if (sz == (long long)HID * 8192) { if (!wq) wq = p; }
        else if (sz == (long long)HID * 1024) { if (!wk) wk = p; else if (!wv) wv = p; }
    }
    float* out = (float*)d_out;

    cudaFuncSetAttribute(qkv_gemm_kernel,
                         cudaFuncAttributeMaxDynamicSharedMemorySize, GEMM_SMEM);

    // 1) convert activations to fp16 (streaming, R11-proven)
    convert_x_kernel<<<2048, 256>>>(x);

    // 2) all weights -> K-major fp16 g_B in one launch (R11-proven)
    convert_w_all_kernel<<<dim3(10, HID), 128>>>(wq, wk, wv);

    // 3) fp16 HMMA GEMM (R14 winner: 128x64, 3 CTAs/SM, frag-DB) + q/k/v scatter
    qkv_gemm_kernel<<<16 * 160, GEMM_THREADS, GEMM_SMEM>>>(out);
}

// round 17
// speedup vs baseline: 1.0764x; 1.0004x over previous
#include <cuda_runtime.h>
#include <cuda_fp16.h>
#include <cstdint>

// ===================== problem sizes =====================
#define SEQ   2048
#define HID   8192
#define NTOT  10240          // 8192 q + 1024 k + 1024 v
#define Q_ELEMS   ((size_t)64 * SEQ * 128)
#define KV_ELEMS  ((size_t)8  * SEQ * 128)

// ===================== scratch (fp16) =====================
__device__ unsigned short g_A[(size_t)SEQ * HID];     // [SEQ][HID]  (M-major)
__device__ unsigned short g_B[(size_t)HID * NTOT];    // [HID][NTOT] (K-major)

// ===================== conversion kernels =====================
__device__ __forceinline__ uint32_t pack2h(float a, float b) {
    uint32_t lo = __half_as_ushort(__float2half_rn(a));
    uint32_t hi = __half_as_ushort(__float2half_rn(b));
    return lo | (hi << 16);
}

// 8 floats/thread, exact grid (no loop): 2 float4 reads + 1 uint4 write.
__global__ void convert_x_kernel(const float* __restrict__ x) {
    size_t t = (size_t)blockIdx.x * blockDim.x + threadIdx.x;  // 8-float chunk
    const float4* s = reinterpret_cast<const float4*>(x) + t * 2;
    float4 v0 = s[0];
    float4 v1 = s[1];
    uint4 h;
    h.x = pack2h(v0.x, v0.y);
    h.y = pack2h(v0.z, v0.w);
    h.z = pack2h(v1.x, v1.y);
    h.w = pack2h(v1.z, v1.w);
    reinterpret_cast<uint4*>(g_A)[t] = h;
}

// All three weights in ONE launch. blockIdx.y = k row; 10 blocks of 128 thr
// cover 1280 8-float chunks = 10240 columns. Region select by column.
__global__ void convert_w_all_kernel(const float* __restrict__ wq,
                                     const float* __restrict__ wk,
                                     const float* __restrict__ wv) {
    int k = blockIdx.y;
    int t = blockIdx.x * blockDim.x + threadIdx.x;    // 8-float chunk, 0..1279
    int n = t * 8;
    const float* src;
    if (n < 8192)       src = wq + (size_t)k * 8192 + n;
    else if (n < 9216)  src = wk + (size_t)k * 1024 + (n - 8192);
    else                src = wv + (size_t)k * 1024 + (n - 9216);
    float4 v0 = reinterpret_cast<const float4*>(src)[0];
    float4 v1 = reinterpret_cast<const float4*>(src)[1];
    uint4 h;
    h.x = pack2h(v0.x, v0.y);
    h.y = pack2h(v0.z, v0.w);
    h.z = pack2h(v1.x, v1.y);
    h.w = pack2h(v1.z, v1.w);
    *reinterpret_cast<uint4*>(&g_B[(size_t)k * NTOT + n]) = h;
}

// ===================== GEMM kernel =====================
// R14 winner (frozen): 128M x 64N, BK=64, 3 stages, 3 CTAs/SM, 12 warps/SM,
// register-fragment double buffering across the 4 ks-steps.
#define GEMM_THREADS 128
#define STAGES       3
#define A_BYTES      16384
#define B_BYTES      8192
#define STAGE_BYTES  (A_BYTES + B_BYTES)     // 24KB
#define GEMM_SMEM    (STAGES * STAGE_BYTES + 1024)

#define LDSM4(r0, r1, r2, r3, addr) \
    asm volatile("ldmatrix.sync.aligned.m8n8.x4.shared.b16 {%0,%1,%2,%3}, [%4];" \
        : "=r"(r0), "=r"(r1), "=r"(r2), "=r"(r3) : "r"(addr))

#define LDSM4T(r0, r1, r2, r3, addr) \
    asm volatile("ldmatrix.sync.aligned.m8n8.x4.trans.shared.b16 {%0,%1,%2,%3}, [%4];" \
        : "=r"(r0), "=r"(r1), "=r"(r2), "=r"(r3) : "r"(addr))

#define MMA_F16(d, a, b0, b1) \
    asm volatile("mma.sync.aligned.m16n8k16.row.col.f32.f16.f16.f32 " \
        "{%0,%1,%2,%3},{%4,%5,%6,%7},{%8,%9},{%0,%1,%2,%3};" \
        : "+f"((d)[0]), "+f"((d)[1]), "+f"((d)[2]), "+f"((d)[3]) \
        : "r"((a)[0]), "r"((a)[1]), "r"((a)[2]), "r"((a)[3]), "r"(b0), "r"(b1))

__device__ __forceinline__ uint32_t smem_to_u32(const void* p) {
    uint32_t addr;
    asm("{ .reg .u64 t; cvta.to.shared.u64 t, %1; cvt.u32.u64 %0, t; }"
        : "=r"(addr) : "l"(p));
    return addr;
}

// A tile: 128 rows x 128B, SW128-swizzled (8 chunks of 16B per row).
__device__ __forceinline__ void cp_tile_a(uint32_t sdst, int m0, int k0, int tid) {
    const char* g = (const char*)(g_A + (size_t)m0 * HID + k0);
    #pragma unroll
    for (int i = 0; i < 8; ++i) {
        int idx = i * GEMM_THREADS + tid;   // 0..1023
        int r = idx >> 3;
        int c = idx & 7;
        uint32_t off = (uint32_t)(r * 128 + ((c ^ (r & 7)) * 16));
        const char* src = g + (size_t)r * (HID * 2) + c * 16;
        asm volatile("cp.async.cg.shared.global [%0], [%1], 16;"
                     :: "r"(sdst + off), "l"(src) : "memory");
    }
}

// B tile: 64 rows(k) x 128B(n=64 fp16), SW128 swizzle keyed on k-row.
__device__ __forceinline__ void cp_tile_b(uint32_t sdst, int n0, int k0, int tid) {
    const char* g = (const char*)(g_B + (size_t)k0 * NTOT + n0);
    #pragma unroll
    for (int i = 0; i < 4; ++i) {
        int idx = i * GEMM_THREADS + tid;   // 0..511
        int r = idx >> 3;                   // k row 0..63
        int c = idx & 7;                    // 16B chunk 0..7
        uint32_t off = (uint32_t)(r * 128 + ((c ^ (r & 7)) * 16));
        const char* src = g + (size_t)r * (NTOT * 2) + c * 16;
        asm volatile("cp.async.cg.shared.global [%0], [%1], 16;"
                     :: "r"(sdst + off), "l"(src) : "memory");
    }
}

__device__ __forceinline__ void load_stage(uint32_t sstage, int m0, int n0,
                                           int k0, int tid) {
    cp_tile_a(sstage,           m0, k0, tid);
    cp_tile_b(sstage + A_BYTES, n0, k0, tid);
    asm volatile("cp.async.commit_group;" ::: "memory");
}

__global__ __launch_bounds__(GEMM_THREADS, 3)
void qkv_gemm_kernel(float* __restrict__ out) {
    extern __shared__ char smem_raw[];
    char* sm = (char*)(((uintptr_t)smem_raw + 1023) & ~(uintptr_t)1023);
    uint32_t sbase = smem_to_u32(sm);

    const int tid  = threadIdx.x;
    const int lane = tid & 31;
    const int wid  = tid >> 5;
    const int warp_m = wid & 1;    // 2 warps along M (64 rows each)
    const int warp_n = wid >> 1;   // 2 warps along N (32 cols each)

    const int m0 = (blockIdx.x & 15) << 7;        // 16 M-tiles (M-fastest)
    const int n0 = (int)(blockIdx.x >> 4) << 6;   // 160 N-tiles of 64

    float acc[4][4][4];
    #pragma unroll
    for (int i = 0; i < 4; ++i)
        #pragma unroll
        for (int j = 0; j < 4; ++j)
            #pragma unroll
            for (int r = 0; r < 4; ++r) acc[i][j][r] = 0.f;

    // A ldmatrix lane roles (non-trans, [M][K] tile, 128B rows)
    const int a_row_l = lane & 15;
    const int a_chi   = lane >> 4;
    // B ldmatrix.trans lane roles ([K][N] tile, 128B rows)
    const int b_krow  = (lane & 7) + ((lane >> 3) & 1) * 8;
    const int b_nchi  = lane >> 4;               // 0/1 -> n8 group within n16

    // Double-buffered register fragments
    uint32_t af[2][4][4];
    uint32_t bf[2][4][2];

    // prologue: prefetch STAGES-1 stages
    load_stage(sbase + 0 * STAGE_BYTES, m0, n0, 0,  tid);
    load_stage(sbase + 1 * STAGE_BYTES, m0, n0, 64, tid);

    const int NKT = HID / 64;   // 128
    for (int kt = 0; kt < NKT; ++kt) {
        if (kt + 2 < NKT)
            asm volatile("cp.async.wait_group 1;" ::: "memory");
        else
            asm volatile("cp.async.wait_group 0;" ::: "memory");
        __syncthreads();

        if (kt + 2 < NKT)
            load_stage(sbase + ((kt + 2) % STAGES) * STAGE_BYTES,
                       m0, n0, (kt + 2) * 64, tid);

        const uint32_t st = sbase + (kt % STAGES) * STAGE_BYTES;
        const uint32_t sa = st;
        const uint32_t sb = st + A_BYTES;

        // frag loader for one ks step into parity buffer p
        auto load_frags = [&](int ks, int p) {
            #pragma unroll
            for (int mf = 0; mf < 4; ++mf) {
                int row = warp_m * 64 + mf * 16 + a_row_l;
                int c   = 2 * ks + a_chi;
                uint32_t off = (uint32_t)(row * 128 + ((c ^ (row & 7)) * 16));
                LDSM4(af[p][mf][0], af[p][mf][1], af[p][mf][2], af[p][mf][3],
                      sa + off);
            }
            #pragma unroll
            for (int jp = 0; jp < 2; ++jp) {
                int krow = ks * 16 + b_krow;
                int nb   = warp_n * 64 + jp * 32 + b_nchi * 16;
                uint32_t off = (uint32_t)(krow * 128
                               + ((((nb >> 4) & 7) ^ (krow & 7)) * 16));
                LDSM4T(bf[p][2*jp][0], bf[p][2*jp][1],
                       bf[p][2*jp+1][0], bf[p][2*jp+1][1], sb + off);
            }
        };

        load_frags(0, 0);
        #pragma unroll
        for (int ks = 0; ks < 4; ++ks) {
            const int cur = ks & 1;
            if (ks < 3) load_frags(ks + 1, cur ^ 1);
            #pragma unroll
            for (int mf = 0; mf < 4; ++mf)
                #pragma unroll
                for (int j = 0; j < 4; ++j)
                    MMA_F16(acc[mf][j], af[cur][mf], bf[cur][j][0], bf[cur][j][1]);
        }
    }

    // ---- epilogue: scatter accumulators to q/k/v head layout ----
    // N-tile (64 cols) = half of one 128-wide head; head index = n0>>7.
    size_t obase;
    if (n0 < 8192)
        obase = (size_t)(n0 >> 7) * ((size_t)SEQ * 128);
    else if (n0 < 9216)
        obase = Q_ELEMS + (size_t)((n0 - 8192) >> 7) * ((size_t)SEQ * 128);
    else
        obase = Q_ELEMS + KV_ELEMS + (size_t)((n0 - 9216) >> 7) * ((size_t)SEQ * 128);
    const int chalf = n0 & 64;   // which half of the head

    const int rbase = m0 + warp_m * 64 + (lane >> 2);
    const int cbase = chalf + warp_n * 32 + (lane & 3) * 2;
    #pragma unroll
    for (int mf = 0; mf < 4; ++mf) {
        #pragma unroll
        for (int j = 0; j < 4; ++j) {
            int m = rbase + mf * 16;
            int c = cbase + j * 8;
            float* p0 = out + obase + (size_t)m * 128 + c;
            p0[0] = acc[mf][j][0];
            p0[1] = acc[mf][j][1];
            float* p1 = p0 + 8 * 128;
            p1[0] = acc[mf][j][2];
            p1[1] = acc[mf][j][3];
        }
    }
}

// ===================== host launcher =====================
extern "C" void kernel_launch(void* const* d_in, const int* in_sizes, int n_in,
                              void* d_out, int out_size) {
    const float* x = nullptr; const float* wq = nullptr;
    const float* wk = nullptr; const float* wv = nullptr;
    for (int i = 0; i < n_in; ++i) {
        long long sz = in_sizes[i];
        const float* p = (const float*)d_in[i];
        if (sz == (long long)SEQ * HID)       { if (!x) x = p; }
        else if (sz == (long long)HID * 8192) { if (!wq) wq = p; }
        else if (sz == (long long)HID * 1024) { if (!wk) wk = p; else if (!wv) wv = p; }
    }
    float* out = (float*)d_out;

    cudaFuncSetAttribute(qkv_gemm_kernel,
                         cudaFuncAttributeMaxDynamicSharedMemorySize, GEMM_SMEM);

    // 1) convert activations to fp16 (8 floats/thread, exact grid)
    //    SEQ*HID/8 = 2,097,152 chunks / 256 thr = 8192 blocks
    convert_x_kernel<<<8192, 256>>>(x);

    // 2) all weights -> K-major fp16 g_B in one launch
    convert_w_all_kernel<<<dim3(10, HID), 128>>>(wq, wk, wv);

    // 3) fp16 HMMA GEMM (R14 winner: 128x64, 3 CTAs/SM, frag-DB) + q/k/v scatter
    qkv_gemm_kernel<<<16 * 160, GEMM_THREADS, GEMM_SMEM>>>(out);
}